// round 2
// baseline (speedup 1.0000x reference)
#include <cuda_runtime.h>
#include <cstdint>

// Problem constants
#define BH      64      // B*H = 4*16
#define SEQ     2048
#define HD      64      // head dim
#define BM      128     // query rows per CTA
#define BK      128     // keys per tile
#define KS_STRIDE 68    // K/V smem row stride (floats) — conflict-free for K B-frags
#define PS_STRIDE 132   // P smem row stride (floats) — conflict-free for A-frags
#define NTHREADS 256

#define SMEM_FLOATS (BK*KS_STRIDE + BM*PS_STRIDE)
#define SMEM_BYTES  (SMEM_FLOATS * 4)

__device__ __forceinline__ uint32_t f2tf32(float x) {
    uint32_t r;
    asm("cvt.rna.tf32.f32 %0, %1;" : "=r"(r) : "f"(x));
    return r;
}

__device__ __forceinline__ void mma_tf32(float* c, const uint32_t* a, uint32_t b0, uint32_t b1) {
    asm volatile(
        "mma.sync.aligned.m16n8k8.row.col.f32.tf32.tf32.f32 "
        "{%0,%1,%2,%3}, {%4,%5,%6,%7}, {%8,%9}, {%0,%1,%2,%3};"
        : "+f"(c[0]), "+f"(c[1]), "+f"(c[2]), "+f"(c[3])
        : "r"(a[0]), "r"(a[1]), "r"(a[2]), "r"(a[3]), "r"(b0), "r"(b1));
}

__global__ __launch_bounds__(NTHREADS, 1)
void attn_kernel(const float* __restrict__ q, const float* __restrict__ k,
                 const float* __restrict__ v, float* __restrict__ out,
                 float* __restrict__ attn)
{
    extern __shared__ float smem[];
    float* Ks = smem;                    // [BK][KS_STRIDE] : K tile (phases A/B), V tile (PV)
    float* Ps = smem + BK * KS_STRIDE;   // [BM][PS_STRIDE] : probability tile

    const int tid  = threadIdx.x;
    const int w    = tid >> 5;
    const int lane = tid & 31;
    const int g    = lane >> 2;   // group-of-4 id (row within fragment)
    const int t    = lane & 3;    // thread within group (col within fragment)
    const int bh   = blockIdx.y;
    const int qt   = blockIdx.x;

    const size_t qoff = ((size_t)bh * SEQ + (size_t)qt * BM) * HD;
    const float* qp = q + qoff;
    const float* kp = k + (size_t)bh * SEQ * HD;
    const float* vp = v + (size_t)bh * SEQ * HD;

    // ---- Stage Q (scaled by 1/8, tf32-rounded) into Ks, then grab A-fragments ----
    #pragma unroll 4
    for (int i = tid; i < BM * (HD / 4); i += NTHREADS) {
        int r = i >> 4, c = (i & 15) * 4;
        float4 val = *(const float4*)(qp + r * HD + c);
        float* dst = Ks + r * KS_STRIDE + c;
        dst[0] = __uint_as_float(f2tf32(val.x * 0.125f));
        dst[1] = __uint_as_float(f2tf32(val.y * 0.125f));
        dst[2] = __uint_as_float(f2tf32(val.z * 0.125f));
        dst[3] = __uint_as_float(f2tf32(val.w * 0.125f));
    }
    __syncthreads();

    uint32_t qa[8][4];   // Q A-fragments for all 8 k-steps (d = 0..63)
    {
        const int r0 = w * 16 + g;
        #pragma unroll
        for (int ks = 0; ks < 8; ks++) {
            qa[ks][0] = __float_as_uint(Ks[r0        * KS_STRIDE + ks * 8 + t    ]);
            qa[ks][1] = __float_as_uint(Ks[(r0 + 8)  * KS_STRIDE + ks * 8 + t    ]);
            qa[ks][2] = __float_as_uint(Ks[r0        * KS_STRIDE + ks * 8 + t + 4]);
            qa[ks][3] = __float_as_uint(Ks[(r0 + 8)  * KS_STRIDE + ks * 8 + t + 4]);
        }
    }
    __syncthreads();

    // ---- Phase A: row sums of exp(scores) ----
    float rs0 = 0.f, rs1 = 0.f;
    #pragma unroll 1
    for (int kt = 0; kt < SEQ / BK; kt++) {
        const float* kpt = kp + (size_t)kt * BK * HD;
        #pragma unroll 4
        for (int i = tid; i < BK * (HD / 4); i += NTHREADS) {
            int r = i >> 4, c = (i & 15) * 4;
            float4 val = *(const float4*)(kpt + r * HD + c);
            float* dst = Ks + r * KS_STRIDE + c;
            dst[0] = __uint_as_float(f2tf32(val.x));
            dst[1] = __uint_as_float(f2tf32(val.y));
            dst[2] = __uint_as_float(f2tf32(val.z));
            dst[3] = __uint_as_float(f2tf32(val.w));
        }
        __syncthreads();

        float sa[16][4];
        #pragma unroll
        for (int nb = 0; nb < 16; nb++) { sa[nb][0]=0.f; sa[nb][1]=0.f; sa[nb][2]=0.f; sa[nb][3]=0.f; }

        #pragma unroll
        for (int ks = 0; ks < 8; ks++) {
            #pragma unroll
            for (int nb = 0; nb < 16; nb++) {
                uint32_t b0 = __float_as_uint(Ks[(nb * 8 + g) * KS_STRIDE + ks * 8 + t    ]);
                uint32_t b1 = __float_as_uint(Ks[(nb * 8 + g) * KS_STRIDE + ks * 8 + t + 4]);
                mma_tf32(sa[nb], qa[ks], b0, b1);
            }
        }
        #pragma unroll
        for (int nb = 0; nb < 16; nb++) {
            rs0 += __expf(sa[nb][0]) + __expf(sa[nb][1]);
            rs1 += __expf(sa[nb][2]) + __expf(sa[nb][3]);
        }
        __syncthreads();
    }
    // reduce across the 4 threads sharing each row
    rs0 += __shfl_xor_sync(0xffffffffu, rs0, 1);
    rs0 += __shfl_xor_sync(0xffffffffu, rs0, 2);
    rs1 += __shfl_xor_sync(0xffffffffu, rs1, 1);
    rs1 += __shfl_xor_sync(0xffffffffu, rs1, 2);
    const float inv0 = 1.0f / rs0;
    const float inv1 = 1.0f / rs1;

    // ---- Phase B: recompute scores, write attn, accumulate O = P @ V ----
    float oc[8][4];
    #pragma unroll
    for (int nb = 0; nb < 8; nb++) { oc[nb][0]=0.f; oc[nb][1]=0.f; oc[nb][2]=0.f; oc[nb][3]=0.f; }

    const int r0 = w * 16 + g;
    float* attn_base = attn + ((size_t)bh * SEQ + (size_t)qt * BM) * SEQ;

    #pragma unroll 1
    for (int kt = 0; kt < SEQ / BK; kt++) {
        // reload K tile
        const float* kpt = kp + (size_t)kt * BK * HD;
        #pragma unroll 4
        for (int i = tid; i < BK * (HD / 4); i += NTHREADS) {
            int r = i >> 4, c = (i & 15) * 4;
            float4 val = *(const float4*)(kpt + r * HD + c);
            float* dst = Ks + r * KS_STRIDE + c;
            dst[0] = __uint_as_float(f2tf32(val.x));
            dst[1] = __uint_as_float(f2tf32(val.y));
            dst[2] = __uint_as_float(f2tf32(val.z));
            dst[3] = __uint_as_float(f2tf32(val.w));
        }
        __syncthreads();

        float sa[16][4];
        #pragma unroll
        for (int nb = 0; nb < 16; nb++) { sa[nb][0]=0.f; sa[nb][1]=0.f; sa[nb][2]=0.f; sa[nb][3]=0.f; }

        #pragma unroll
        for (int ks = 0; ks < 8; ks++) {
            #pragma unroll
            for (int nb = 0; nb < 16; nb++) {
                uint32_t b0 = __float_as_uint(Ks[(nb * 8 + g) * KS_STRIDE + ks * 8 + t    ]);
                uint32_t b1 = __float_as_uint(Ks[(nb * 8 + g) * KS_STRIDE + ks * 8 + t + 4]);
                mma_tf32(sa[nb], qa[ks], b0, b1);
            }
        }

        // normalized probabilities -> Ps (full fp32)
        #pragma unroll
        for (int nb = 0; nb < 16; nb++) {
            float p0 = __expf(sa[nb][0]) * inv0;
            float p1 = __expf(sa[nb][1]) * inv0;
            float p2 = __expf(sa[nb][2]) * inv1;
            float p3 = __expf(sa[nb][3]) * inv1;
            *(float2*)&Ps[r0       * PS_STRIDE + nb * 8 + 2 * t] = make_float2(p0, p1);
            *(float2*)&Ps[(r0 + 8) * PS_STRIDE + nb * 8 + 2 * t] = make_float2(p2, p3);
        }
        __syncthreads();   // Ks fully consumed, Ps complete

        // coalesced attn write (the dominant HBM traffic)
        {
            float* ap = attn_base + kt * BK;
            #pragma unroll 4
            for (int i = tid; i < BM * (BK / 4); i += NTHREADS) {
                int r = i >> 5, c = (i & 31) * 4;
                *(float4*)(ap + (size_t)r * SEQ + c) = *(float4*)&Ps[r * PS_STRIDE + c];
            }
        }

        // load V tile into Ks (tf32-rounded)
        const float* vpt = vp + (size_t)kt * BK * HD;
        #pragma unroll 4
        for (int i = tid; i < BK * (HD / 4); i += NTHREADS) {
            int r = i >> 4, c = (i & 15) * 4;
            float4 val = *(const float4*)(vpt + r * HD + c);
            float* dst = Ks + r * KS_STRIDE + c;
            dst[0] = __uint_as_float(f2tf32(val.x));
            dst[1] = __uint_as_float(f2tf32(val.y));
            dst[2] = __uint_as_float(f2tf32(val.z));
            dst[3] = __uint_as_float(f2tf32(val.w));
        }
        __syncthreads();

        // O += P @ V
        #pragma unroll
        for (int kb = 0; kb < 16; kb++) {
            uint32_t pa[4];
            pa[0] = f2tf32(Ps[r0       * PS_STRIDE + kb * 8 + t    ]);
            pa[1] = f2tf32(Ps[(r0 + 8) * PS_STRIDE + kb * 8 + t    ]);
            pa[2] = f2tf32(Ps[r0       * PS_STRIDE + kb * 8 + t + 4]);
            pa[3] = f2tf32(Ps[(r0 + 8) * PS_STRIDE + kb * 8 + t + 4]);
            #pragma unroll
            for (int nb = 0; nb < 8; nb++) {
                uint32_t b0 = __float_as_uint(Ks[(kb * 8 + t    ) * KS_STRIDE + nb * 8 + g]);
                uint32_t b1 = __float_as_uint(Ks[(kb * 8 + t + 4) * KS_STRIDE + nb * 8 + g]);
                mma_tf32(oc[nb], pa, b0, b1);
            }
        }
        __syncthreads();   // Ks consumed before next iteration's K load
    }

    // ---- write O ----
    float* op = out + qoff;
    #pragma unroll
    for (int nb = 0; nb < 8; nb++) {
        *(float2*)(op + r0       * HD + nb * 8 + 2 * t) = make_float2(oc[nb][0], oc[nb][1]);
        *(float2*)(op + (r0 + 8) * HD + nb * 8 + 2 * t) = make_float2(oc[nb][2], oc[nb][3]);
    }
}

extern "C" void kernel_launch(void* const* d_in, const int* in_sizes, int n_in,
                              void* d_out, int out_size)
{
    const float* q = (const float*)d_in[0];
    const float* k = (const float*)d_in[1];
    const float* v = (const float*)d_in[2];
    float* out  = (float*)d_out;
    float* attn = out + (size_t)BH * SEQ * HD;   // output first, then attn

    cudaFuncSetAttribute(attn_kernel, cudaFuncAttributeMaxDynamicSharedMemorySize, SMEM_BYTES);

    dim3 grid(SEQ / BM, BH);   // x = q-tile (fast), y = bh -> concurrent CTAs share K/V in L2
    attn_kernel<<<grid, NTHREADS, SMEM_BYTES>>>(q, k, v, out, attn);
}

// round 4
// speedup vs baseline: 1.3167x; 1.3167x over previous
#include <cuda_runtime.h>
#include <cstdint>

// Problem constants
#define BH      64      // B*H = 4*16
#define SEQ     2048
#define HD      64      // head dim
#define BM      128     // query rows per CTA
#define BK      128     // keys per tile
#define KS_STRIDE 68    // K/V smem row stride (floats)
#define PS_STRIDE 132   // P smem row stride (floats)
#define NTHREADS 256

#define SMEM_FLOATS (BK*KS_STRIDE + BM*PS_STRIDE)
#define SMEM_BYTES  (SMEM_FLOATS * 4)

__device__ __forceinline__ uint32_t f2tf32(float x) {
    uint32_t r;
    asm("cvt.rna.tf32.f32 %0, %1;" : "=r"(r) : "f"(x));
    return r;
}

__device__ __forceinline__ float ex2(float x) {
    float y;
    asm("ex2.approx.f32 %0, %1;" : "=f"(y) : "f"(x));
    return y;
}

__device__ __forceinline__ void ldsm4(uint32_t* r, uint32_t addr) {
    asm volatile("ldmatrix.sync.aligned.m8n8.x4.shared.b16 {%0,%1,%2,%3}, [%4];"
        : "=r"(r[0]), "=r"(r[1]), "=r"(r[2]), "=r"(r[3]) : "r"(addr));
}

__device__ __forceinline__ void mma_tf32(float* c, const uint32_t* a, uint32_t b0, uint32_t b1) {
    asm volatile(
        "mma.sync.aligned.m16n8k8.row.col.f32.tf32.tf32.f32 "
        "{%0,%1,%2,%3}, {%4,%5,%6,%7}, {%8,%9}, {%0,%1,%2,%3};"
        : "+f"(c[0]), "+f"(c[1]), "+f"(c[2]), "+f"(c[3])
        : "r"(a[0]), "r"(a[1]), "r"(a[2]), "r"(a[3]), "r"(b0), "r"(b1));
}

__global__ __launch_bounds__(NTHREADS, 2)
void attn_kernel(const float* __restrict__ q, const float* __restrict__ k,
                 const float* __restrict__ v, float* __restrict__ out,
                 float* __restrict__ attn)
{
    extern __shared__ float smem[];
    float* Ks = smem;                    // [BK][KS_STRIDE] : Q (prologue), K, V tiles
    float* Ps = smem + BK * KS_STRIDE;   // [BM][PS_STRIDE] : probability tile

    const uint32_t ks_u32 = (uint32_t)__cvta_generic_to_shared(Ks);
    const uint32_t ps_u32 = (uint32_t)__cvta_generic_to_shared(Ps);

    const int tid  = threadIdx.x;
    const int w    = tid >> 5;
    const int lane = tid & 31;
    const int g    = lane >> 2;   // fragment row-group
    const int t    = lane & 3;    // fragment col-in-group
    const int bh   = blockIdx.y;
    const int qt   = blockIdx.x;
    const int r0   = w * 16 + g;

    const size_t qoff = ((size_t)bh * SEQ + (size_t)qt * BM) * HD;
    const float* qp = q + qoff;
    const float* kp = k + (size_t)bh * SEQ * HD;
    const float* vp = v + (size_t)bh * SEQ * HD;

    // ldmatrix per-lane addresses:
    //  B-frag (K rows = n-dim): row-in-matrix = lane&7, d-col block = (lane>>3)*4
    const uint32_t baddr = ks_u32 + (uint32_t)((lane & 7) * KS_STRIDE + (lane >> 3) * 4) * 4;
    //  A-frag (Q in Ks / P in Ps)
    const int a_row = w * 16 + (lane & 7) + 8 * ((lane >> 3) & 1);
    const int a_colq = (lane >> 4) * 4;
    const uint32_t qaddr = ks_u32 + (uint32_t)(a_row * KS_STRIDE + a_colq) * 4;
    const uint32_t paddr = ps_u32 + (uint32_t)(a_row * PS_STRIDE + a_colq) * 4;

    // exp(s) == 2^(s*log2e); fold log2e and 1/temperature into Q scale.
    const float QSCALE = 0.125f * 1.44269504088896f;

    // ---- Stage Q (scaled, tf32-rounded) into Ks, grab A-fragments via ldmatrix ----
    #pragma unroll 4
    for (int i = tid; i < BM * (HD / 4); i += NTHREADS) {
        int r = i >> 4, c = (i & 15) * 4;
        float4 val = *(const float4*)(qp + r * HD + c);
        float* dst = Ks + r * KS_STRIDE + c;
        dst[0] = __uint_as_float(f2tf32(val.x * QSCALE));
        dst[1] = __uint_as_float(f2tf32(val.y * QSCALE));
        dst[2] = __uint_as_float(f2tf32(val.z * QSCALE));
        dst[3] = __uint_as_float(f2tf32(val.w * QSCALE));
    }
    __syncthreads();

    uint32_t qa[8][4];   // Q A-fragments for k-steps d=0..63
    #pragma unroll
    for (int ks = 0; ks < 8; ks++) ldsm4(qa[ks], qaddr + ks * 32);
    __syncthreads();

    // ---- Phase A: row sums of 2^(scores) ----
    float rs0 = 0.f, rs1 = 0.f;
    #pragma unroll 1
    for (int kt = 0; kt < SEQ / BK; kt++) {
        const float* kpt = kp + (size_t)kt * BK * HD;
        #pragma unroll 4
        for (int i = tid; i < BK * (HD / 4); i += NTHREADS) {
            int r = i >> 4, c = (i & 15) * 4;
            float4 val = *(const float4*)(kpt + r * HD + c);
            float* dst = Ks + r * KS_STRIDE + c;
            dst[0] = __uint_as_float(f2tf32(val.x));
            dst[1] = __uint_as_float(f2tf32(val.y));
            dst[2] = __uint_as_float(f2tf32(val.z));
            dst[3] = __uint_as_float(f2tf32(val.w));
        }
        __syncthreads();

        uint32_t bb = baddr;
        #pragma unroll
        for (int nb = 0; nb < 16; nb++) {
            float sa[4] = {0.f, 0.f, 0.f, 0.f};
            #pragma unroll
            for (int ksq = 0; ksq < 4; ksq++) {
                uint32_t b[4];
                ldsm4(b, bb + ksq * 64);
                mma_tf32(sa, qa[2 * ksq],     b[0], b[1]);
                mma_tf32(sa, qa[2 * ksq + 1], b[2], b[3]);
            }
            rs0 += ex2(sa[0]) + ex2(sa[1]);
            rs1 += ex2(sa[2]) + ex2(sa[3]);
            bb += 8 * KS_STRIDE * 4;
        }
        __syncthreads();
    }
    rs0 += __shfl_xor_sync(0xffffffffu, rs0, 1);
    rs0 += __shfl_xor_sync(0xffffffffu, rs0, 2);
    rs1 += __shfl_xor_sync(0xffffffffu, rs1, 1);
    rs1 += __shfl_xor_sync(0xffffffffu, rs1, 2);
    const float inv0 = 1.0f / rs0;
    const float inv1 = 1.0f / rs1;

    // ---- Phase B: recompute scores, write attn, accumulate O = P @ V ----
    float oc[8][4];
    #pragma unroll
    for (int nb = 0; nb < 8; nb++) { oc[nb][0]=0.f; oc[nb][1]=0.f; oc[nb][2]=0.f; oc[nb][3]=0.f; }

    float* attn_base = attn + ((size_t)bh * SEQ + (size_t)qt * BM) * SEQ;

    #pragma unroll 1
    for (int kt = 0; kt < SEQ / BK; kt++) {
        // reload K tile
        const float* kpt = kp + (size_t)kt * BK * HD;
        #pragma unroll 4
        for (int i = tid; i < BK * (HD / 4); i += NTHREADS) {
            int r = i >> 4, c = (i & 15) * 4;
            float4 val = *(const float4*)(kpt + r * HD + c);
            float* dst = Ks + r * KS_STRIDE + c;
            dst[0] = __uint_as_float(f2tf32(val.x));
            dst[1] = __uint_as_float(f2tf32(val.y));
            dst[2] = __uint_as_float(f2tf32(val.z));
            dst[3] = __uint_as_float(f2tf32(val.w));
        }
        __syncthreads();

        uint32_t bb = baddr;
        float* ap = attn_base + kt * BK;
        #pragma unroll
        for (int nb = 0; nb < 16; nb++) {
            float sa[4] = {0.f, 0.f, 0.f, 0.f};
            #pragma unroll
            for (int ksq = 0; ksq < 4; ksq++) {
                uint32_t b[4];
                ldsm4(b, bb + ksq * 64);
                mma_tf32(sa, qa[2 * ksq],     b[0], b[1]);
                mma_tf32(sa, qa[2 * ksq + 1], b[2], b[3]);
            }
            float p0 = ex2(sa[0]) * inv0;
            float p1 = ex2(sa[1]) * inv0;
            float p2 = ex2(sa[2]) * inv1;
            float p3 = ex2(sa[3]) * inv1;
            // stage into Ps for the PV MMA
            *(float2*)&Ps[r0       * PS_STRIDE + nb * 8 + 2 * t] = make_float2(p0, p1);
            *(float2*)&Ps[(r0 + 8) * PS_STRIDE + nb * 8 + 2 * t] = make_float2(p2, p3);
            // direct coalesced-sector store of attn
            *(float2*)(ap + (size_t) r0      * SEQ + nb * 8 + 2 * t) = make_float2(p0, p1);
            *(float2*)(ap + (size_t)(r0 + 8) * SEQ + nb * 8 + 2 * t) = make_float2(p2, p3);
            bb += 8 * KS_STRIDE * 4;
        }
        __syncthreads();   // Ks fully consumed by QK, Ps complete

        // load V tile into Ks (tf32-rounded)
        const float* vpt = vp + (size_t)kt * BK * HD;
        #pragma unroll 4
        for (int i = tid; i < BK * (HD / 4); i += NTHREADS) {
            int r = i >> 4, c = (i & 15) * 4;
            float4 val = *(const float4*)(vpt + r * HD + c);
            float* dst = Ks + r * KS_STRIDE + c;
            dst[0] = __uint_as_float(f2tf32(val.x));
            dst[1] = __uint_as_float(f2tf32(val.y));
            dst[2] = __uint_as_float(f2tf32(val.z));
            dst[3] = __uint_as_float(f2tf32(val.w));
        }
        __syncthreads();

        // O += P @ V
        #pragma unroll
        for (int kb = 0; kb < 16; kb++) {
            uint32_t pa[4];
            ldsm4(pa, paddr + kb * 32);
            pa[0] = f2tf32(__uint_as_float(pa[0]));
            pa[1] = f2tf32(__uint_as_float(pa[1]));
            pa[2] = f2tf32(__uint_as_float(pa[2]));
            pa[3] = f2tf32(__uint_as_float(pa[3]));
            #pragma unroll
            for (int nb = 0; nb < 8; nb++) {
                uint32_t b0 = __float_as_uint(Ks[(kb * 8 + t    ) * KS_STRIDE + nb * 8 + g]);
                uint32_t b1 = __float_as_uint(Ks[(kb * 8 + t + 4) * KS_STRIDE + nb * 8 + g]);
                mma_tf32(oc[nb], pa, b0, b1);
            }
        }
        __syncthreads();   // Ks/Ps consumed before next iteration
    }

    // ---- write O ----
    float* op = out + qoff;
    #pragma unroll
    for (int nb = 0; nb < 8; nb++) {
        *(float2*)(op + r0       * HD + nb * 8 + 2 * t) = make_float2(oc[nb][0], oc[nb][1]);
        *(float2*)(op + (r0 + 8) * HD + nb * 8 + 2 * t) = make_float2(oc[nb][2], oc[nb][3]);
    }
}

extern "C" void kernel_launch(void* const* d_in, const int* in_sizes, int n_in,
                              void* d_out, int out_size)
{
    const float* q = (const float*)d_in[0];
    const float* k = (const float*)d_in[1];
    const float* v = (const float*)d_in[2];
    float* out  = (float*)d_out;
    float* attn = out + (size_t)BH * SEQ * HD;   // output first, then attn

    cudaFuncSetAttribute(attn_kernel, cudaFuncAttributeMaxDynamicSharedMemorySize, SMEM_BYTES);

    dim3 grid(SEQ / BM, BH);   // x = q-tile (fast), y = bh -> concurrent CTAs share K/V in L2
    attn_kernel<<<grid, NTHREADS, SMEM_BYTES>>>(q, k, v, out, attn);
}

// round 5
// speedup vs baseline: 1.4284x; 1.0849x over previous
#include <cuda_runtime.h>
#include <cstdint>

// Problem constants
#define BH      64      // B*H = 4*16
#define SEQ     2048
#define HD      64      // head dim
#define BM      128     // query rows per CTA
#define BK      128     // keys per tile
#define KS_STRIDE 68    // K smem row stride (floats) — ldsm-clean (17 mod 8 = 1)
#define VS_STRIDE 72    // V smem row stride (floats) — conflict-free scalar B loads (8t+g)
#define PS_STRIDE 132   // P smem row stride (floats) — ldsm-clean (33 mod 8 = 1)
#define NTHREADS 256

#define KV_FLOATS  (BK * VS_STRIDE)                 // union buffer holds K (stride 68) or V (stride 72)
#define SMEM_FLOATS (KV_FLOATS + BM * PS_STRIDE)
#define SMEM_BYTES  (SMEM_FLOATS * 4)

__device__ __forceinline__ uint32_t f2tf32(float x) {
    uint32_t r;
    asm("cvt.rna.tf32.f32 %0, %1;" : "=r"(r) : "f"(x));
    return r;
}

__device__ __forceinline__ float ex2(float x) {
    float y;
    asm("ex2.approx.f32 %0, %1;" : "=f"(y) : "f"(x));
    return y;
}

__device__ __forceinline__ void ldsm4(uint32_t* r, uint32_t addr) {
    asm volatile("ldmatrix.sync.aligned.m8n8.x4.shared.b16 {%0,%1,%2,%3}, [%4];"
        : "=r"(r[0]), "=r"(r[1]), "=r"(r[2]), "=r"(r[3]) : "r"(addr));
}

__device__ __forceinline__ void mma_tf32(float* c, const uint32_t* a, uint32_t b0, uint32_t b1) {
    asm volatile(
        "mma.sync.aligned.m16n8k8.row.col.f32.tf32.tf32.f32 "
        "{%0,%1,%2,%3}, {%4,%5,%6,%7}, {%8,%9}, {%0,%1,%2,%3};"
        : "+f"(c[0]), "+f"(c[1]), "+f"(c[2]), "+f"(c[3])
        : "r"(a[0]), "r"(a[1]), "r"(a[2]), "r"(a[3]), "r"(b0), "r"(b1));
}

__global__ __launch_bounds__(NTHREADS, 2)
void attn_kernel(const float* __restrict__ q, const float* __restrict__ k,
                 const float* __restrict__ v, float* __restrict__ out,
                 float* __restrict__ attn)
{
    extern __shared__ float smem[];
    float* Ks = smem;                  // K tile [BK][68] or V tile [BK][72]
    float* Ps = smem + KV_FLOATS;      // P tile [BM][132]; also rowsum scratch [2][128]

    const uint32_t ks_u32 = (uint32_t)__cvta_generic_to_shared(Ks);
    const uint32_t ps_u32 = (uint32_t)__cvta_generic_to_shared(Ps);

    const int tid  = threadIdx.x;
    const int w    = tid >> 5;
    const int lane = tid & 31;
    const int g    = lane >> 2;
    const int t    = lane & 3;
    const int wm   = w & 3;     // m-warp: rows wm*32 .. wm*32+31
    const int wn   = w >> 2;    // n-warp: cols wn*64 .. wn*64+63 (QK) / wn*32.. (PV)
    const int bh   = blockIdx.y;
    const int qt   = blockIdx.x;

    const size_t qoff = ((size_t)bh * SEQ + (size_t)qt * BM) * HD;
    const float* qp = q + qoff;
    const float* kp = k + (size_t)bh * SEQ * HD;
    const float* vp = v + (size_t)bh * SEQ * HD;

    // ldmatrix lane addresses
    const int a_row = wm * 32 + (lane & 7) + 8 * ((lane >> 3) & 1);
    const uint32_t qaddr = ks_u32 + (uint32_t)(a_row * KS_STRIDE + (lane >> 4) * 4) * 4;
    const uint32_t paddr = ps_u32 + (uint32_t)(a_row * PS_STRIDE + (lane >> 4) * 4) * 4;
    const uint32_t baddr = ks_u32 + (uint32_t)((wn * 64 + (lane & 7)) * KS_STRIDE + (lane >> 3) * 4) * 4;

    // exp(s) == 2^(s*log2e); fold log2e and 1/temperature into Q scale.
    const float QSCALE = 0.125f * 1.44269504088896f;

    // ---- Stage Q (scaled, tf32-rounded), keep A-fragments resident ----
    #pragma unroll 4
    for (int i = tid; i < BM * (HD / 4); i += NTHREADS) {
        int r = i >> 4, c = (i & 15) * 4;
        float4 val = *(const float4*)(qp + r * HD + c);
        float* dst = Ks + r * KS_STRIDE + c;
        dst[0] = __uint_as_float(f2tf32(val.x * QSCALE));
        dst[1] = __uint_as_float(f2tf32(val.y * QSCALE));
        dst[2] = __uint_as_float(f2tf32(val.z * QSCALE));
        dst[3] = __uint_as_float(f2tf32(val.w * QSCALE));
    }
    __syncthreads();

    uint32_t qa[2][8][4];   // [mb][k-step][frag] : rows wm*32 + mb*16 + ...
    #pragma unroll
    for (int mb = 0; mb < 2; mb++)
        #pragma unroll
        for (int ks = 0; ks < 8; ks++)
            ldsm4(qa[mb][ks], qaddr + (uint32_t)(mb * 16 * KS_STRIDE * 4) + ks * 32);
    __syncthreads();

    // ---- Phase A: partial row sums of 2^(scores) over this warp's 64 cols ----
    float rs[2][2] = {{0.f, 0.f}, {0.f, 0.f}};
    #pragma unroll 1
    for (int kt = 0; kt < SEQ / BK; kt++) {
        const float* kpt = kp + (size_t)kt * BK * HD;
        #pragma unroll 4
        for (int i = tid; i < BK * (HD / 4); i += NTHREADS) {
            int r = i >> 4, c = (i & 15) * 4;
            float4 val = *(const float4*)(kpt + r * HD + c);
            float* dst = Ks + r * KS_STRIDE + c;
            dst[0] = __uint_as_float(f2tf32(val.x));
            dst[1] = __uint_as_float(f2tf32(val.y));
            dst[2] = __uint_as_float(f2tf32(val.z));
            dst[3] = __uint_as_float(f2tf32(val.w));
        }
        __syncthreads();

        uint32_t bb = baddr;
        #pragma unroll
        for (int nb = 0; nb < 8; nb++) {
            float sa0[4] = {0.f,0.f,0.f,0.f};
            float sa1[4] = {0.f,0.f,0.f,0.f};
            #pragma unroll
            for (int ksq = 0; ksq < 4; ksq++) {
                uint32_t b[4];
                ldsm4(b, bb + ksq * 64);
                mma_tf32(sa0, qa[0][2*ksq],   b[0], b[1]);
                mma_tf32(sa0, qa[0][2*ksq+1], b[2], b[3]);
                mma_tf32(sa1, qa[1][2*ksq],   b[0], b[1]);
                mma_tf32(sa1, qa[1][2*ksq+1], b[2], b[3]);
            }
            rs[0][0] += ex2(sa0[0]) + ex2(sa0[1]);
            rs[0][1] += ex2(sa0[2]) + ex2(sa0[3]);
            rs[1][0] += ex2(sa1[0]) + ex2(sa1[1]);
            rs[1][1] += ex2(sa1[2]) + ex2(sa1[3]);
            bb += 8 * KS_STRIDE * 4;
        }
        __syncthreads();
    }

    // cross-warp rowsum combine: reduce over t-lanes, publish per n-half, sum halves
    float* rsum = Ps;   // [2][128] floats, Ps not yet in use
    #pragma unroll
    for (int mb = 0; mb < 2; mb++)
        #pragma unroll
        for (int rg = 0; rg < 2; rg++) {
            float vsum = rs[mb][rg];
            vsum += __shfl_xor_sync(0xffffffffu, vsum, 1);
            vsum += __shfl_xor_sync(0xffffffffu, vsum, 2);
            if (t == 0) rsum[wn * 128 + wm * 32 + mb * 16 + rg * 8 + g] = vsum;
        }
    __syncthreads();
    float inv[2][2];
    #pragma unroll
    for (int mb = 0; mb < 2; mb++)
        #pragma unroll
        for (int rg = 0; rg < 2; rg++) {
            int r = wm * 32 + mb * 16 + rg * 8 + g;
            inv[mb][rg] = 1.0f / (rsum[r] + rsum[128 + r]);
        }

    // ---- Phase B ----
    float oc[2][4][4];   // [mb][nb][frag] : O tile 32x32 per warp (cols wn*32..)
    #pragma unroll
    for (int mb = 0; mb < 2; mb++)
        #pragma unroll
        for (int nb = 0; nb < 4; nb++)
            { oc[mb][nb][0]=0.f; oc[mb][nb][1]=0.f; oc[mb][nb][2]=0.f; oc[mb][nb][3]=0.f; }

    float* attn_base = attn + ((size_t)bh * SEQ + (size_t)qt * BM) * SEQ;

    #pragma unroll 1
    for (int kt = 0; kt < SEQ / BK; kt++) {
        const float* kpt = kp + (size_t)kt * BK * HD;
        #pragma unroll 4
        for (int i = tid; i < BK * (HD / 4); i += NTHREADS) {
            int r = i >> 4, c = (i & 15) * 4;
            float4 val = *(const float4*)(kpt + r * HD + c);
            float* dst = Ks + r * KS_STRIDE + c;
            dst[0] = __uint_as_float(f2tf32(val.x));
            dst[1] = __uint_as_float(f2tf32(val.y));
            dst[2] = __uint_as_float(f2tf32(val.z));
            dst[3] = __uint_as_float(f2tf32(val.w));
        }
        __syncthreads();

        uint32_t bb = baddr;
        float* ap = attn_base + kt * BK;
        #pragma unroll
        for (int nb = 0; nb < 8; nb++) {
            float sa0[4] = {0.f,0.f,0.f,0.f};
            float sa1[4] = {0.f,0.f,0.f,0.f};
            #pragma unroll
            for (int ksq = 0; ksq < 4; ksq++) {
                uint32_t b[4];
                ldsm4(b, bb + ksq * 64);
                mma_tf32(sa0, qa[0][2*ksq],   b[0], b[1]);
                mma_tf32(sa0, qa[0][2*ksq+1], b[2], b[3]);
                mma_tf32(sa1, qa[1][2*ksq],   b[0], b[1]);
                mma_tf32(sa1, qa[1][2*ksq+1], b[2], b[3]);
            }
            const int col = wn * 64 + nb * 8 + 2 * t;
            const int r00 = wm * 32 + g;
            {
                float p0 = ex2(sa0[0]) * inv[0][0];
                float p1 = ex2(sa0[1]) * inv[0][0];
                float p2 = ex2(sa0[2]) * inv[0][1];
                float p3 = ex2(sa0[3]) * inv[0][1];
                *(float2*)&Ps[ r00      * PS_STRIDE + col] = make_float2(p0, p1);
                *(float2*)&Ps[(r00 + 8) * PS_STRIDE + col] = make_float2(p2, p3);
                *(float2*)(ap + (size_t) r00      * SEQ + col) = make_float2(p0, p1);
                *(float2*)(ap + (size_t)(r00 + 8) * SEQ + col) = make_float2(p2, p3);
            }
            {
                float p0 = ex2(sa1[0]) * inv[1][0];
                float p1 = ex2(sa1[1]) * inv[1][0];
                float p2 = ex2(sa1[2]) * inv[1][1];
                float p3 = ex2(sa1[3]) * inv[1][1];
                *(float2*)&Ps[(r00 + 16) * PS_STRIDE + col] = make_float2(p0, p1);
                *(float2*)&Ps[(r00 + 24) * PS_STRIDE + col] = make_float2(p2, p3);
                *(float2*)(ap + (size_t)(r00 + 16) * SEQ + col) = make_float2(p0, p1);
                *(float2*)(ap + (size_t)(r00 + 24) * SEQ + col) = make_float2(p2, p3);
            }
            bb += 8 * KS_STRIDE * 4;
        }
        __syncthreads();   // K consumed, Ps complete

        // load V tile (stride 72, tf32-rounded)
        const float* vpt = vp + (size_t)kt * BK * HD;
        #pragma unroll 4
        for (int i = tid; i < BK * (HD / 4); i += NTHREADS) {
            int r = i >> 4, c = (i & 15) * 4;
            float4 val = *(const float4*)(vpt + r * HD + c);
            float* dst = Ks + r * VS_STRIDE + c;
            dst[0] = __uint_as_float(f2tf32(val.x));
            dst[1] = __uint_as_float(f2tf32(val.y));
            dst[2] = __uint_as_float(f2tf32(val.z));
            dst[3] = __uint_as_float(f2tf32(val.w));
        }
        __syncthreads();

        // O += P @ V  (V B-loads conflict-free: banks = 8t + g + const)
        #pragma unroll
        for (int kb = 0; kb < 16; kb++) {
            uint32_t pa[2][4];
            #pragma unroll
            for (int mb = 0; mb < 2; mb++) {
                ldsm4(pa[mb], paddr + (uint32_t)(mb * 16 * PS_STRIDE * 4) + kb * 32);
                pa[mb][0] = f2tf32(__uint_as_float(pa[mb][0]));
                pa[mb][1] = f2tf32(__uint_as_float(pa[mb][1]));
                pa[mb][2] = f2tf32(__uint_as_float(pa[mb][2]));
                pa[mb][3] = f2tf32(__uint_as_float(pa[mb][3]));
            }
            #pragma unroll
            for (int nb = 0; nb < 4; nb++) {
                uint32_t b0 = __float_as_uint(Ks[(kb * 8 + t    ) * VS_STRIDE + wn * 32 + nb * 8 + g]);
                uint32_t b1 = __float_as_uint(Ks[(kb * 8 + t + 4) * VS_STRIDE + wn * 32 + nb * 8 + g]);
                mma_tf32(oc[0][nb], pa[0], b0, b1);
                mma_tf32(oc[1][nb], pa[1], b0, b1);
            }
        }
        __syncthreads();   // V consumed before next K load
    }

    // ---- write O (cols wn*32 + nb*8 + 2t, rows wm*32 + mb*16 + g/+8) ----
    float* op = out + qoff;
    #pragma unroll
    for (int mb = 0; mb < 2; mb++) {
        const int r00 = wm * 32 + mb * 16 + g;
        #pragma unroll
        for (int nb = 0; nb < 4; nb++) {
            const int col = wn * 32 + nb * 8 + 2 * t;
            *(float2*)(op + r00      * HD + col) = make_float2(oc[mb][nb][0], oc[mb][nb][1]);
            *(float2*)(op + (r00+8)  * HD + col) = make_float2(oc[mb][nb][2], oc[mb][nb][3]);
        }
    }
}

extern "C" void kernel_launch(void* const* d_in, const int* in_sizes, int n_in,
                              void* d_out, int out_size)
{
    const float* q = (const float*)d_in[0];
    const float* k = (const float*)d_in[1];
    const float* v = (const float*)d_in[2];
    float* out  = (float*)d_out;
    float* attn = out + (size_t)BH * SEQ * HD;   // output first, then attn

    cudaFuncSetAttribute(attn_kernel, cudaFuncAttributeMaxDynamicSharedMemorySize, SMEM_BYTES);

    dim3 grid(SEQ / BM, BH);
    attn_kernel<<<grid, NTHREADS, SMEM_BYTES>>>(q, k, v, out, attn);
}

// round 6
// speedup vs baseline: 1.5026x; 1.0519x over previous
#include <cuda_runtime.h>
#include <cstdint>

// Problem constants
#define BH      64      // B*H
#define SEQ     2048
#define HD      64
#define BM      128     // query rows per CTA
#define BK      128     // keys per tile
#define NT      (SEQ/BK)  // 16 key tiles
#define KS      68      // K smem row stride (floats) — ldsm-clean (4r mod 32 distinct)
#define VS      72      // V smem row stride (floats) — conflict-free scalar B loads (8t+g)
#define PS      132     // P smem row stride (floats) — ldsm-clean
#define NTHREADS 512

// smem layout (float offsets)
#define OFF_K0  0
#define OFF_K1  (BK*KS)                 // 8704
#define OFF_V0  (2*BK*KS)               // 17408
#define OFF_V1  (2*BK*KS + BK*VS)       // 26624
#define OFF_PS  (2*BK*KS + 2*BK*VS)     // 35840
#define SMEM_FLOATS (OFF_PS + BM*PS)    // 52736
#define SMEM_BYTES  (SMEM_FLOATS * 4)   // 210944

__device__ __forceinline__ uint32_t f2tf32(float x) {
    uint32_t r;
    asm("cvt.rna.tf32.f32 %0, %1;" : "=r"(r) : "f"(x));
    return r;
}

__device__ __forceinline__ float ex2(float x) {
    float y;
    asm("ex2.approx.f32 %0, %1;" : "=f"(y) : "f"(x));
    return y;
}

__device__ __forceinline__ void ldsm4(uint32_t* r, uint32_t addr) {
    asm volatile("ldmatrix.sync.aligned.m8n8.x4.shared.b16 {%0,%1,%2,%3}, [%4];"
        : "=r"(r[0]), "=r"(r[1]), "=r"(r[2]), "=r"(r[3]) : "r"(addr));
}

__device__ __forceinline__ void mma_tf32(float* c, const uint32_t* a, uint32_t b0, uint32_t b1) {
    asm volatile(
        "mma.sync.aligned.m16n8k8.row.col.f32.tf32.tf32.f32 "
        "{%0,%1,%2,%3}, {%4,%5,%6,%7}, {%8,%9}, {%0,%1,%2,%3};"
        : "+f"(c[0]), "+f"(c[1]), "+f"(c[2]), "+f"(c[3])
        : "r"(a[0]), "r"(a[1]), "r"(a[2]), "r"(a[3]), "r"(b0), "r"(b1));
}

__device__ __forceinline__ void cpa16(uint32_t dst, const void* src) {
    asm volatile("cp.async.ca.shared.global [%0], [%1], 16;" :: "r"(dst), "l"(src) : "memory");
}
__device__ __forceinline__ void cpa_commit() { asm volatile("cp.async.commit_group;" ::: "memory"); }
__device__ __forceinline__ void cpa_wait0()  { asm volatile("cp.async.wait_group 0;" ::: "memory"); }

// copy one 128x64 fp32 tile (raw) into smem with row stride `stride` floats
__device__ __forceinline__ void copy_tile(uint32_t smem_base_bytes, int off_floats, int stride,
                                          const float* src, int tid) {
    uint32_t dst0 = smem_base_bytes + (uint32_t)off_floats * 4;
    #pragma unroll
    for (int j = 0; j < 4; j++) {
        int c  = tid + j * NTHREADS;      // 0..2047 16B-chunks
        int r  = c >> 4;                  // 16 chunks per 64-float row
        int c4 = (c & 15) * 4;
        cpa16(dst0 + (uint32_t)(r * stride + c4) * 4, src + r * HD + c4);
    }
}

__global__ __launch_bounds__(NTHREADS, 1)
void attn_kernel(const float* __restrict__ q, const float* __restrict__ k,
                 const float* __restrict__ v, float* __restrict__ out,
                 float* __restrict__ attn)
{
    extern __shared__ float smem[];
    const uint32_t sb = (uint32_t)__cvta_generic_to_shared(smem);

    const int tid  = threadIdx.x;
    const int w    = tid >> 5;
    const int lane = tid & 31;
    const int g    = lane >> 2;
    const int t    = lane & 3;
    const int wm   = w & 3;     // m-warp: rows wm*32..+31
    const int wn   = w >> 2;    // n-warp: S-cols wn*32..+31 (QK), O-cols wn*16..+15 (PV)
    const int bh   = blockIdx.y;
    const int qt   = blockIdx.x;

    const size_t qoff = ((size_t)bh * SEQ + (size_t)qt * BM) * HD;
    const float* qp = q + qoff;
    const float* kp = k + (size_t)bh * SEQ * HD;
    const float* vp = v + (size_t)bh * SEQ * HD;

    // ldmatrix lane addresses
    const int a_row = wm * 32 + (lane & 7) + 8 * ((lane >> 3) & 1);
    const int a_col = (lane >> 4) * 4;
    const uint32_t qaddr = sb + (uint32_t)(OFF_K0 + a_row * KS + a_col) * 4;
    const uint32_t paddr = sb + (uint32_t)(OFF_PS + a_row * PS + a_col) * 4;
    const uint32_t boff  = (uint32_t)((wn * 32 + (lane & 7)) * KS + (lane >> 3) * 4) * 4;

    const float QSCALE = 0.125f * 1.44269504088896f;   // (1/temp) * log2(e)

    // ---- Stage Q (scaled, tf32-rounded) into K0, keep A-fragments resident ----
    #pragma unroll
    for (int i = tid; i < BM * (HD / 4); i += NTHREADS) {
        int r = i >> 4, c = (i & 15) * 4;
        float4 val = *(const float4*)(qp + r * HD + c);
        float* dst = smem + OFF_K0 + r * KS + c;
        dst[0] = __uint_as_float(f2tf32(val.x * QSCALE));
        dst[1] = __uint_as_float(f2tf32(val.y * QSCALE));
        dst[2] = __uint_as_float(f2tf32(val.z * QSCALE));
        dst[3] = __uint_as_float(f2tf32(val.w * QSCALE));
    }
    __syncthreads();

    uint32_t qa[2][8][4];
    #pragma unroll
    for (int mb = 0; mb < 2; mb++)
        #pragma unroll
        for (int ks = 0; ks < 8; ks++)
            ldsm4(qa[mb][ks], qaddr + (uint32_t)(mb * 16 * KS * 4) + ks * 32);
    __syncthreads();

    // ---- Phase A: partial row sums of 2^(scores) over this warp's 32 cols ----
    copy_tile(sb, OFF_K0, KS, kp, tid);   // K tile 0 (overwrites Q staging; qa already resident)
    cpa_commit();

    float rs[2][2] = {{0.f, 0.f}, {0.f, 0.f}};
    #pragma unroll 1
    for (int kt = 0; kt < NT; kt++) {
        cpa_wait0();
        __syncthreads();
        if (kt + 1 < NT) {
            copy_tile(sb, (kt & 1) ? OFF_K0 : OFF_K1, KS, kp + (size_t)(kt + 1) * BK * HD, tid);
            cpa_commit();
        }
        uint32_t bb = sb + (uint32_t)((kt & 1) ? OFF_K1 : OFF_K0) * 4 + boff;
        #pragma unroll
        for (int nb = 0; nb < 4; nb++) {
            float sa0[4] = {0.f,0.f,0.f,0.f};
            float sa1[4] = {0.f,0.f,0.f,0.f};
            #pragma unroll
            for (int ksq = 0; ksq < 4; ksq++) {
                uint32_t b[4];
                ldsm4(b, bb + ksq * 64);
                b[0] = f2tf32(__uint_as_float(b[0]));
                b[1] = f2tf32(__uint_as_float(b[1]));
                b[2] = f2tf32(__uint_as_float(b[2]));
                b[3] = f2tf32(__uint_as_float(b[3]));
                mma_tf32(sa0, qa[0][2*ksq],   b[0], b[1]);
                mma_tf32(sa0, qa[0][2*ksq+1], b[2], b[3]);
                mma_tf32(sa1, qa[1][2*ksq],   b[0], b[1]);
                mma_tf32(sa1, qa[1][2*ksq+1], b[2], b[3]);
            }
            rs[0][0] += ex2(sa0[0]) + ex2(sa0[1]);
            rs[0][1] += ex2(sa0[2]) + ex2(sa0[3]);
            rs[1][0] += ex2(sa1[0]) + ex2(sa1[1]);
            rs[1][1] += ex2(sa1[2]) + ex2(sa1[3]);
            bb += 8 * KS * 4;
        }
        __syncthreads();
    }

    // cross-warp rowsum combine via Ps scratch (4 n-warps)
    float* rsum = smem + OFF_PS;   // [4][128]
    #pragma unroll
    for (int mb = 0; mb < 2; mb++)
        #pragma unroll
        for (int rg = 0; rg < 2; rg++) {
            float vsum = rs[mb][rg];
            vsum += __shfl_xor_sync(0xffffffffu, vsum, 1);
            vsum += __shfl_xor_sync(0xffffffffu, vsum, 2);
            if (t == 0) rsum[wn * 128 + wm * 32 + mb * 16 + rg * 8 + g] = vsum;
        }
    __syncthreads();
    float inv[2][2];
    #pragma unroll
    for (int mb = 0; mb < 2; mb++)
        #pragma unroll
        for (int rg = 0; rg < 2; rg++) {
            int r = wm * 32 + mb * 16 + rg * 8 + g;
            inv[mb][rg] = 1.0f / (rsum[r] + rsum[128 + r] + rsum[256 + r] + rsum[384 + r]);
        }
    __syncthreads();

    // ---- Phase B: recompute scores, write attn, accumulate O = P @ V ----
    float oc[2][2][4];
    #pragma unroll
    for (int mb = 0; mb < 2; mb++)
        #pragma unroll
        for (int nb = 0; nb < 2; nb++)
            { oc[mb][nb][0]=0.f; oc[mb][nb][1]=0.f; oc[mb][nb][2]=0.f; oc[mb][nb][3]=0.f; }

    float* attn_base = attn + ((size_t)bh * SEQ + (size_t)qt * BM) * SEQ;

    copy_tile(sb, OFF_K0, KS, kp, tid);
    copy_tile(sb, OFF_V0, VS, vp, tid);
    cpa_commit();

    #pragma unroll 1
    for (int kt = 0; kt < NT; kt++) {
        cpa_wait0();
        __syncthreads();
        if (kt + 1 < NT) {
            copy_tile(sb, (kt & 1) ? OFF_K0 : OFF_K1, KS, kp + (size_t)(kt + 1) * BK * HD, tid);
            copy_tile(sb, (kt & 1) ? OFF_V0 : OFF_V1, VS, vp + (size_t)(kt + 1) * BK * HD, tid);
            cpa_commit();
        }
        uint32_t bb = sb + (uint32_t)((kt & 1) ? OFF_K1 : OFF_K0) * 4 + boff;
        const float* Vs = smem + ((kt & 1) ? OFF_V1 : OFF_V0);
        float* ap = attn_base + kt * BK;

        #pragma unroll
        for (int nb = 0; nb < 4; nb++) {
            float sa0[4] = {0.f,0.f,0.f,0.f};
            float sa1[4] = {0.f,0.f,0.f,0.f};
            #pragma unroll
            for (int ksq = 0; ksq < 4; ksq++) {
                uint32_t b[4];
                ldsm4(b, bb + ksq * 64);
                b[0] = f2tf32(__uint_as_float(b[0]));
                b[1] = f2tf32(__uint_as_float(b[1]));
                b[2] = f2tf32(__uint_as_float(b[2]));
                b[3] = f2tf32(__uint_as_float(b[3]));
                mma_tf32(sa0, qa[0][2*ksq],   b[0], b[1]);
                mma_tf32(sa0, qa[0][2*ksq+1], b[2], b[3]);
                mma_tf32(sa1, qa[1][2*ksq],   b[0], b[1]);
                mma_tf32(sa1, qa[1][2*ksq+1], b[2], b[3]);
            }
            const int col = wn * 32 + nb * 8 + 2 * t;
            const int r00 = wm * 32 + g;
            float* PsW = smem + OFF_PS;
            {
                float p0 = ex2(sa0[0]) * inv[0][0];
                float p1 = ex2(sa0[1]) * inv[0][0];
                float p2 = ex2(sa0[2]) * inv[0][1];
                float p3 = ex2(sa0[3]) * inv[0][1];
                *(float2*)&PsW[ r00      * PS + col] = make_float2(p0, p1);
                *(float2*)&PsW[(r00 + 8) * PS + col] = make_float2(p2, p3);
                *(float2*)(ap + (size_t) r00      * SEQ + col) = make_float2(p0, p1);
                *(float2*)(ap + (size_t)(r00 + 8) * SEQ + col) = make_float2(p2, p3);
            }
            {
                float p0 = ex2(sa1[0]) * inv[1][0];
                float p1 = ex2(sa1[1]) * inv[1][0];
                float p2 = ex2(sa1[2]) * inv[1][1];
                float p3 = ex2(sa1[3]) * inv[1][1];
                *(float2*)&PsW[(r00 + 16) * PS + col] = make_float2(p0, p1);
                *(float2*)&PsW[(r00 + 24) * PS + col] = make_float2(p2, p3);
                *(float2*)(ap + (size_t)(r00 + 16) * SEQ + col) = make_float2(p0, p1);
                *(float2*)(ap + (size_t)(r00 + 24) * SEQ + col) = make_float2(p2, p3);
            }
            bb += 8 * KS * 4;
        }
        __syncthreads();   // Ps complete, K consumed

        // O += P @ V   (V scalar B-loads conflict-free: bank = 8t+g+const)
        const int vcol = wn * 16 + g;
        #pragma unroll
        for (int kb = 0; kb < 16; kb++) {
            uint32_t pa[2][4];
            #pragma unroll
            for (int mb = 0; mb < 2; mb++) {
                ldsm4(pa[mb], paddr + (uint32_t)(mb * 16 * PS * 4) + kb * 32);
                pa[mb][0] = f2tf32(__uint_as_float(pa[mb][0]));
                pa[mb][1] = f2tf32(__uint_as_float(pa[mb][1]));
                pa[mb][2] = f2tf32(__uint_as_float(pa[mb][2]));
                pa[mb][3] = f2tf32(__uint_as_float(pa[mb][3]));
            }
            #pragma unroll
            for (int nb = 0; nb < 2; nb++) {
                uint32_t b0 = f2tf32(Vs[(kb * 8 + t    ) * VS + vcol + nb * 8]);
                uint32_t b1 = f2tf32(Vs[(kb * 8 + t + 4) * VS + vcol + nb * 8]);
                mma_tf32(oc[0][nb], pa[0], b0, b1);
                mma_tf32(oc[1][nb], pa[1], b0, b1);
            }
        }
        // next loop-top barrier protects Ps/V from overwrite
    }

    // ---- write O ----
    float* op = out + qoff;
    #pragma unroll
    for (int mb = 0; mb < 2; mb++) {
        const int r00 = wm * 32 + mb * 16 + g;
        #pragma unroll
        for (int nb = 0; nb < 2; nb++) {
            const int col = wn * 16 + nb * 8 + 2 * t;
            *(float2*)(op + r00       * HD + col) = make_float2(oc[mb][nb][0], oc[mb][nb][1]);
            *(float2*)(op + (r00 + 8) * HD + col) = make_float2(oc[mb][nb][2], oc[mb][nb][3]);
        }
    }
}

extern "C" void kernel_launch(void* const* d_in, const int* in_sizes, int n_in,
                              void* d_out, int out_size)
{
    const float* q = (const float*)d_in[0];
    const float* k = (const float*)d_in[1];
    const float* v = (const float*)d_in[2];
    float* out  = (float*)d_out;
    float* attn = out + (size_t)BH * SEQ * HD;   // output first, then attn

    cudaFuncSetAttribute(attn_kernel, cudaFuncAttributeMaxDynamicSharedMemorySize, SMEM_BYTES);

    dim3 grid(SEQ / BM, BH);
    attn_kernel<<<grid, NTHREADS, SMEM_BYTES>>>(q, k, v, out, attn);
}